// round 1
// baseline (speedup 1.0000x reference)
#include <cuda_runtime.h>
#include <cuda_fp16.h>
#include <cstdint>

// Problem constants
#define BB 4
#define SS 2048
#define EE 1024
#define HH 16
#define DD 64
#define MM (BB*SS)   // 8192 rows

// ---------------------------------------------------------------------------
// Scratch (device globals: no allocation allowed in kernel_launch)
// ---------------------------------------------------------------------------
__device__ __half g_Q[MM * EE];   // projected Q, [B*S, E] fp16
__device__ __half g_K[MM * EE];
__device__ __half g_V[MM * EE];
__device__ __half g_A[MM * EE];   // attention output, [B*S, E] fp16

// ---------------------------------------------------------------------------
// PTX helpers: ldmatrix + mma.sync m16n8k16 fp16 (fp32 accum)
// ---------------------------------------------------------------------------
__device__ __forceinline__ uint32_t smem_u32(const void* p) {
    return (uint32_t)__cvta_generic_to_shared(p);
}
__device__ __forceinline__ void ldmx4(uint32_t& r0, uint32_t& r1, uint32_t& r2,
                                      uint32_t& r3, uint32_t a) {
    asm volatile("ldmatrix.sync.aligned.m8n8.x4.shared.b16 {%0,%1,%2,%3}, [%4];\n"
                 : "=r"(r0), "=r"(r1), "=r"(r2), "=r"(r3) : "r"(a));
}
__device__ __forceinline__ void ldmx4t(uint32_t& r0, uint32_t& r1, uint32_t& r2,
                                       uint32_t& r3, uint32_t a) {
    asm volatile("ldmatrix.sync.aligned.m8n8.x4.trans.shared.b16 {%0,%1,%2,%3}, [%4];\n"
                 : "=r"(r0), "=r"(r1), "=r"(r2), "=r"(r3) : "r"(a));
}
__device__ __forceinline__ void mma16816(float* c, const uint32_t* a, const uint32_t* b) {
    asm volatile(
        "mma.sync.aligned.m16n8k16.row.col.f32.f16.f16.f32 "
        "{%0,%1,%2,%3}, {%4,%5,%6,%7}, {%8,%9}, {%0,%1,%2,%3};\n"
        : "+f"(c[0]), "+f"(c[1]), "+f"(c[2]), "+f"(c[3])
        : "r"(a[0]), "r"(a[1]), "r"(a[2]), "r"(a[3]), "r"(b[0]), "r"(b[1]));
}

// ---------------------------------------------------------------------------
// GEMM:  C[M,N] = A[M,K] * W[N,K]^T + bias   (NT layout, K contiguous both)
// Tiles: BM=128 BN=128 BK=32, 256 threads (8 warps as 4(m) x 2(n)),
// warp tile 32x64. Padded smem stride 40 halves -> conflict-free ldmatrix.
// ---------------------------------------------------------------------------
#define BM 128
#define BN 128
#define BK 32
#define KST 40

template <bool A16, bool O16>
__device__ __forceinline__ void gemm_body(const void* Ag_, const float* Wg,
                                          const float* biasg, void* Cg_,
                                          __half* sA, __half* sB) {
    const int tid = threadIdx.x;
    const int bm = blockIdx.x, bn = blockIdx.y;
    const int warp = tid >> 5, lane = tid & 31;
    const int wm = warp & 3, wn = warp >> 2;

    const int lr = tid >> 3;        // 0..31: row group
    const int lc = (tid & 7) * 4;   // 4-element column chunk in K

    const float*  Af = (const float*)Ag_;
    const __half* Ah = (const __half*)Ag_;

    float4 avf[4], bvf[4];
    uint2  avh[4];

    auto load_tile = [&](int kt) {
        const int kb = kt * BK + lc;
#pragma unroll
        for (int i = 0; i < 4; i++) {
            const int row = lr + i * 32;
            const long ga = (long)(bm * BM + row) * EE + kb;
            if (A16) avh[i] = *(const uint2*)(Ah + ga);
            else     avf[i] = *(const float4*)(Af + ga);
            const long gb = (long)(bn * BN + row) * EE + kb;
            bvf[i] = *(const float4*)(Wg + gb);
        }
    };
    auto store_tile = [&](int buf) {
        __half* dA = sA + buf * (BM * KST);
        __half* dB = sB + buf * (BM * KST);
#pragma unroll
        for (int i = 0; i < 4; i++) {
            const int row = lr + i * 32;
            if (A16) {
                *(uint2*)(dA + row * KST + lc) = avh[i];
            } else {
                *(__half2*)(dA + row * KST + lc)     = __floats2half2_rn(avf[i].x, avf[i].y);
                *(__half2*)(dA + row * KST + lc + 2) = __floats2half2_rn(avf[i].z, avf[i].w);
            }
            *(__half2*)(dB + row * KST + lc)     = __floats2half2_rn(bvf[i].x, bvf[i].y);
            *(__half2*)(dB + row * KST + lc + 2) = __floats2half2_rn(bvf[i].z, bvf[i].w);
        }
    };

    load_tile(0);
    store_tile(0);
    __syncthreads();

    float acc[2][8][4];
#pragma unroll
    for (int j = 0; j < 2; j++)
#pragma unroll
        for (int n = 0; n < 8; n++)
#pragma unroll
            for (int v = 0; v < 4; v++) acc[j][n][v] = 0.f;

    const int NK = EE / BK;  // 32 k-tiles
    int buf = 0;
    for (int kt = 0; kt < NK; kt++) {
        if (kt + 1 < NK) load_tile(kt + 1);      // gmem prefetch into regs
        __half* cA = sA + buf * (BM * KST);
        __half* cB = sB + buf * (BM * KST);
#pragma unroll
        for (int ks = 0; ks < 2; ks++) {
            const int kb = ks * 16;
            uint32_t af[2][4];
#pragma unroll
            for (int j = 0; j < 2; j++) {
                const uint32_t ad = smem_u32(
                    cA + (wm * 32 + j * 16 + (lane & 15)) * KST + kb + (lane >> 4) * 8);
                ldmx4(af[j][0], af[j][1], af[j][2], af[j][3], ad);
            }
            uint32_t bf[8][2];
#pragma unroll
            for (int q = 0; q < 4; q++) {
                const int nrow = wn * 64 + q * 16 + (lane & 7) + ((lane >> 4) << 3);
                const int koff = ((lane >> 3) & 1) * 8;
                const uint32_t ad = smem_u32(cB + nrow * KST + kb + koff);
                ldmx4(bf[2 * q][0], bf[2 * q][1], bf[2 * q + 1][0], bf[2 * q + 1][1], ad);
            }
#pragma unroll
            for (int j = 0; j < 2; j++)
#pragma unroll
                for (int n = 0; n < 8; n++) mma16816(acc[j][n], af[j], bf[n]);
        }
        if (kt + 1 < NK) store_tile(buf ^ 1);
        __syncthreads();
        buf ^= 1;
    }

    // Epilogue: + bias, convert, store
#pragma unroll
    for (int j = 0; j < 2; j++) {
#pragma unroll
        for (int n = 0; n < 8; n++) {
            const int row = bm * BM + wm * 32 + j * 16 + (lane >> 2);
            const int col = bn * BN + wn * 64 + n * 8 + (lane & 3) * 2;
            const float b0 = biasg[col], b1 = biasg[col + 1];
            const float c0 = acc[j][n][0] + b0, c1 = acc[j][n][1] + b1;
            const float c2 = acc[j][n][2] + b0, c3 = acc[j][n][3] + b1;
            if (O16) {
                __half* C = (__half*)Cg_;
                *(__half2*)(C + (long)row * EE + col)       = __floats2half2_rn(c0, c1);
                *(__half2*)(C + (long)(row + 8) * EE + col) = __floats2half2_rn(c2, c3);
            } else {
                float* C = (float*)Cg_;
                *(float2*)(C + (long)row * EE + col)       = make_float2(c0, c1);
                *(float2*)(C + (long)(row + 8) * EE + col) = make_float2(c2, c3);
            }
        }
    }
}

__global__ __launch_bounds__(256, 1) void qkv_kernel(
    const float* xq, const float* xk, const float* xv,
    const float* Wq, const float* Wk, const float* Wv,
    const float* bq, const float* bk, const float* bv) {
    __shared__ __half sA[2 * BM * KST];
    __shared__ __half sB[2 * BM * KST];
    const float* X; const float* W; const float* bias; __half* O;
    if (blockIdx.z == 0)      { X = xq; W = Wq; bias = bq; O = g_Q; }
    else if (blockIdx.z == 1) { X = xk; W = Wk; bias = bk; O = g_K; }
    else                      { X = xv; W = Wv; bias = bv; O = g_V; }
    gemm_body<false, true>(X, W, bias, O, sA, sB);
}

__global__ __launch_bounds__(256, 1) void oproj_kernel(const float* Wo, const float* bo,
                                                       float* out) {
    __shared__ __half sA[2 * BM * KST];
    __shared__ __half sB[2 * BM * KST];
    gemm_body<true, false>(g_A, Wo, bo, out, sA, sB);
}

// ---------------------------------------------------------------------------
// Flash attention: one CTA = (b, h, 128 queries). 8 warps x 16 queries.
// KV tiles of 64. Scores never touch memory; QK^T accumulator layout is
// reused directly as the PV A-fragment (register-resident P).
// ---------------------------------------------------------------------------
#define QT 128
#define KT 64
#define AST 72   // padded smem stride (halves): conflict-free ldmatrix

__global__ __launch_bounds__(256, 1) void attn_kernel() {
    __shared__ __half sQ[QT * AST];
    __shared__ __half sK[KT * AST];
    __shared__ __half sV[KT * AST];

    const int tid  = threadIdx.x;
    const int warp = tid >> 5, lane = tid & 31;
    const int qbase   = blockIdx.x * QT;
    const int h       = blockIdx.y;
    const int b       = blockIdx.z;
    const long rowbase = (long)b * SS;
    const int colbase  = h * DD;

    // Load Q tile [128 x 64] fp16 (strided rows of the [M,1024] layout)
    {
        const int lr = tid >> 3;
        const int lc = (tid & 7) * 8;
#pragma unroll
        for (int i = 0; i < 4; i++) {
            const int row = lr + i * 32;
            const uint4 v = *(const uint4*)(g_Q + (rowbase + qbase + row) * EE + colbase + lc);
            *(uint4*)(sQ + row * AST + lc) = v;
        }
    }
    __syncthreads();

    // Per-warp persistent Q fragments: 16 rows x 64 d
    uint32_t qa[4][4];
    {
        const int wq = warp * 16;
#pragma unroll
        for (int kk = 0; kk < 4; kk++) {
            const uint32_t ad =
                smem_u32(sQ + (wq + (lane & 15)) * AST + kk * 16 + (lane >> 4) * 8);
            ldmx4(qa[kk][0], qa[kk][1], qa[kk][2], qa[kk][3], ad);
        }
    }

    float oacc[8][4];
#pragma unroll
    for (int n = 0; n < 8; n++)
#pragma unroll
        for (int v = 0; v < 4; v++) oacc[n][v] = 0.f;
    float m0 = -1e30f, m1 = -1e30f, l0 = 0.f, l1 = 0.f;

    const float SC = 0.125f * 1.4426950408889634f;  // scale * log2(e)

    for (int t = 0; t < SS / KT; t++) {
        // Stage K,V tiles through registers (lets gmem latency overlap prev compute)
        const int lr = tid >> 3;
        const int lc = (tid & 7) * 8;
        uint4 kreg[2], vreg[2];
#pragma unroll
        for (int i = 0; i < 2; i++) {
            const int row = lr + i * 32;
            const long ga = (rowbase + t * KT + row) * EE + colbase + lc;
            kreg[i] = *(const uint4*)(g_K + ga);
            vreg[i] = *(const uint4*)(g_V + ga);
        }
        __syncthreads();  // prior iteration's smem reads complete
#pragma unroll
        for (int i = 0; i < 2; i++) {
            const int row = lr + i * 32;
            *(uint4*)(sK + row * AST + lc) = kreg[i];
            *(uint4*)(sV + row * AST + lc) = vreg[i];
        }
        __syncthreads();

        // S = Q K^T : 16 x 64 per warp
        float sacc[8][4];
#pragma unroll
        for (int n = 0; n < 8; n++)
#pragma unroll
            for (int v = 0; v < 4; v++) sacc[n][v] = 0.f;
#pragma unroll
        for (int kk = 0; kk < 4; kk++) {
            uint32_t kb[8][2];
#pragma unroll
            for (int q = 0; q < 4; q++) {
                const int nrow = q * 16 + (lane & 7) + ((lane >> 4) << 3);
                const int koff = ((lane >> 3) & 1) * 8;
                const uint32_t ad = smem_u32(sK + nrow * AST + kk * 16 + koff);
                ldmx4(kb[2 * q][0], kb[2 * q][1], kb[2 * q + 1][0], kb[2 * q + 1][1], ad);
            }
#pragma unroll
            for (int n = 0; n < 8; n++) mma16816(sacc[n], qa[kk], kb[n]);
        }

        // Online softmax (rows: lane/4 and lane/4 + 8)
        float mx0 = -1e30f, mx1 = -1e30f;
#pragma unroll
        for (int n = 0; n < 8; n++) {
            mx0 = fmaxf(mx0, fmaxf(sacc[n][0], sacc[n][1]));
            mx1 = fmaxf(mx1, fmaxf(sacc[n][2], sacc[n][3]));
        }
        mx0 = fmaxf(mx0, __shfl_xor_sync(0xffffffffu, mx0, 1));
        mx0 = fmaxf(mx0, __shfl_xor_sync(0xffffffffu, mx0, 2));
        mx1 = fmaxf(mx1, __shfl_xor_sync(0xffffffffu, mx1, 1));
        mx1 = fmaxf(mx1, __shfl_xor_sync(0xffffffffu, mx1, 2));
        const float nm0 = fmaxf(m0, mx0 * SC);
        const float nm1 = fmaxf(m1, mx1 * SC);
        const float cr0 = exp2f(m0 - nm0);
        const float cr1 = exp2f(m1 - nm1);
        m0 = nm0; m1 = nm1;
        l0 *= cr0; l1 *= cr1;
#pragma unroll
        for (int n = 0; n < 8; n++) {
            oacc[n][0] *= cr0; oacc[n][1] *= cr0;
            oacc[n][2] *= cr1; oacc[n][3] *= cr1;
        }
        float rs0 = 0.f, rs1 = 0.f;
        uint32_t pa[8], pb[8];
#pragma unroll
        for (int n = 0; n < 8; n++) {
            const float p0 = exp2f(sacc[n][0] * SC - m0);
            const float p1 = exp2f(sacc[n][1] * SC - m0);
            const float p2 = exp2f(sacc[n][2] * SC - m1);
            const float p3 = exp2f(sacc[n][3] * SC - m1);
            rs0 += p0 + p1; rs1 += p2 + p3;
            const __half2 hp0 = __floats2half2_rn(p0, p1);
            const __half2 hp1 = __floats2half2_rn(p2, p3);
            pa[n] = *(const uint32_t*)&hp0;
            pb[n] = *(const uint32_t*)&hp1;
        }
        rs0 += __shfl_xor_sync(0xffffffffu, rs0, 1);
        rs0 += __shfl_xor_sync(0xffffffffu, rs0, 2);
        rs1 += __shfl_xor_sync(0xffffffffu, rs1, 1);
        rs1 += __shfl_xor_sync(0xffffffffu, rs1, 2);
        l0 += rs0; l1 += rs1;

        // O += P V  (P already in A-fragment layout)
#pragma unroll
        for (int kk = 0; kk < 4; kk++) {
            const uint32_t af[4] = {pa[2 * kk], pb[2 * kk], pa[2 * kk + 1], pb[2 * kk + 1]};
            uint32_t vb[8][2];
#pragma unroll
            for (int pr = 0; pr < 4; pr++) {
                const int kvrow = kk * 16 + (((lane >> 3) & 1) << 3) + (lane & 7);
                const int dcol  = pr * 16 + ((lane >> 4) << 3);
                const uint32_t ad = smem_u32(sV + kvrow * AST + dcol);
                ldmx4t(vb[2 * pr][0], vb[2 * pr][1], vb[2 * pr + 1][0], vb[2 * pr + 1][1], ad);
            }
#pragma unroll
            for (int n = 0; n < 8; n++) mma16816(oacc[n], af, vb[n]);
        }
    }

    // Epilogue: O / l -> fp16, natural [M, 1024] layout
    const float il0 = 1.f / l0, il1 = 1.f / l1;
    const int row = qbase + warp * 16 + (lane >> 2);
#pragma unroll
    for (int n = 0; n < 8; n++) {
        const int col = colbase + n * 8 + (lane & 3) * 2;
        *(__half2*)(g_A + (rowbase + row) * EE + col) =
            __floats2half2_rn(oacc[n][0] * il0, oacc[n][1] * il0);
        *(__half2*)(g_A + (rowbase + row + 8) * EE + col) =
            __floats2half2_rn(oacc[n][2] * il1, oacc[n][3] * il1);
    }
}

// ---------------------------------------------------------------------------
// Launch
// ---------------------------------------------------------------------------
extern "C" void kernel_launch(void* const* d_in, const int* in_sizes, int n_in,
                              void* d_out, int out_size) {
    (void)in_sizes; (void)n_in; (void)out_size;
    const float* q  = (const float*)d_in[0];
    const float* k  = (const float*)d_in[1];
    const float* v  = (const float*)d_in[2];
    const float* Wq = (const float*)d_in[3];
    const float* bq = (const float*)d_in[4];
    const float* Wk = (const float*)d_in[5];
    const float* bk = (const float*)d_in[6];
    const float* Wv = (const float*)d_in[7];
    const float* bv = (const float*)d_in[8];
    const float* Wo = (const float*)d_in[9];
    const float* bo = (const float*)d_in[10];

    dim3 g1(MM / BM, EE / BN, 3);
    qkv_kernel<<<g1, 256>>>(q, k, v, Wq, Wk, Wv, bq, bk, bv);

    dim3 g2(SS / QT, HH, BB);
    attn_kernel<<<g2, 256>>>();

    dim3 g3(MM / BM, EE / BN, 1);
    oproj_kernel<<<g3, 256>>>(Wo, bo, (float*)d_out);
}

// round 2
// speedup vs baseline: 1.4411x; 1.4411x over previous
#include <cuda_runtime.h>
#include <cuda_fp16.h>
#include <cstdint>

// Problem constants
#define BB 4
#define SS 2048
#define EE 1024
#define HH 16
#define DD 64
#define MM (BB*SS)   // 8192 rows

// ---------------------------------------------------------------------------
// Scratch (device globals)
// ---------------------------------------------------------------------------
__device__ __half g_Q[MM * EE];
__device__ __half g_K[MM * EE];
__device__ __half g_V[MM * EE];
__device__ __half g_A[MM * EE];
__device__ __half g_X[3][MM * EE];   // fp16-converted inputs q,k,v
__device__ __half g_W[4][EE * EE];   // fp16-converted weights Wq,Wk,Wv,Wo

// ---------------------------------------------------------------------------
// PTX helpers
// ---------------------------------------------------------------------------
__device__ __forceinline__ uint32_t smem_u32(const void* p) {
    return (uint32_t)__cvta_generic_to_shared(p);
}
__device__ __forceinline__ void ldmx4(uint32_t& r0, uint32_t& r1, uint32_t& r2,
                                      uint32_t& r3, uint32_t a) {
    asm volatile("ldmatrix.sync.aligned.m8n8.x4.shared.b16 {%0,%1,%2,%3}, [%4];\n"
                 : "=r"(r0), "=r"(r1), "=r"(r2), "=r"(r3) : "r"(a));
}
__device__ __forceinline__ void ldmx4t(uint32_t& r0, uint32_t& r1, uint32_t& r2,
                                       uint32_t& r3, uint32_t a) {
    asm volatile("ldmatrix.sync.aligned.m8n8.x4.trans.shared.b16 {%0,%1,%2,%3}, [%4];\n"
                 : "=r"(r0), "=r"(r1), "=r"(r2), "=r"(r3) : "r"(a));
}
__device__ __forceinline__ void mma16816(float* c, const uint32_t* a, const uint32_t* b) {
    asm volatile(
        "mma.sync.aligned.m16n8k16.row.col.f32.f16.f16.f32 "
        "{%0,%1,%2,%3}, {%4,%5,%6,%7}, {%8,%9}, {%0,%1,%2,%3};\n"
        : "+f"(c[0]), "+f"(c[1]), "+f"(c[2]), "+f"(c[3])
        : "r"(a[0]), "r"(a[1]), "r"(a[2]), "r"(a[3]), "r"(b[0]), "r"(b[1]));
}
__device__ __forceinline__ void cpa16(uint32_t dst, const void* src) {
    asm volatile("cp.async.cg.shared.global [%0], [%1], 16;\n" :: "r"(dst), "l"(src));
}
__device__ __forceinline__ void cpcommit() { asm volatile("cp.async.commit_group;\n"); }
template <int N>
__device__ __forceinline__ void cpwait() { asm volatile("cp.async.wait_group %0;\n" :: "n"(N)); }

// ---------------------------------------------------------------------------
// fp32 -> fp16 conversion of all inputs/weights in one pass
// ---------------------------------------------------------------------------
__global__ void cvt_kernel(const float* q, const float* k, const float* v,
                           const float* Wq, const float* Wk, const float* Wv,
                           const float* Wo) {
    const long X4 = (long)MM * EE / 4;   // 2097152 float4 per input
    const long W4 = (long)EE * EE / 4;   // 262144  float4 per weight
    const long total = 3 * X4 + 4 * W4;
    for (long i = (long)blockIdx.x * blockDim.x + threadIdx.x; i < total;
         i += (long)gridDim.x * blockDim.x) {
        const float* src; __half* dst; long off;
        if (i < X4)          { src = q; dst = g_X[0]; off = i; }
        else if (i < 2 * X4) { src = k; dst = g_X[1]; off = i - X4; }
        else if (i < 3 * X4) { src = v; dst = g_X[2]; off = i - 2 * X4; }
        else {
            long j = i - 3 * X4;
            int w = (int)(j >> 18);      // j / W4
            off = j & (W4 - 1);
            src = (w == 0) ? Wq : (w == 1) ? Wk : (w == 2) ? Wv : Wo;
            dst = g_W[w];
        }
        const float4 f = *(const float4*)(src + off * 4);
        const __half2 h0 = __floats2half2_rn(f.x, f.y);
        const __half2 h1 = __floats2half2_rn(f.z, f.w);
        uint2 h;
        h.x = *(const uint32_t*)&h0;
        h.y = *(const uint32_t*)&h1;
        *(uint2*)(dst + off * 4) = h;
    }
}

// ---------------------------------------------------------------------------
// GEMM: C[M,N] = A[M,K]*W[N,K]^T + bias, fp16 in / fp32 accum
// BM=BN=128, BK=32, 3-stage cp.async pipeline, 256 thr (4x2 warps, 32x64 warp
// tile), padded stride 40 halves (80B) -> conflict-free, 2 CTAs/SM.
// ---------------------------------------------------------------------------
#define BM 128
#define BN 128
#define BK 32
#define KST 40
#define STG 3
#define STAGE_H (BM * KST)             // halves per operand per stage

template <bool O16>
__device__ __forceinline__ void gemm_body(const __half* Ag, const __half* Wg,
                                          const float* biasg, void* Cg_,
                                          __half* sA, __half* sB) {
    const int tid = threadIdx.x;
    const int bm = blockIdx.x, bn = blockIdx.y;
    const int warp = tid >> 5, lane = tid & 31;
    const int wm = warp & 3, wn = warp >> 2;

    // cp.async mapping: thread -> (row=tid/4, 16B chunk=(tid&3)), rows +0/+64
    const int lrow = tid >> 2;
    const int lch  = (tid & 3) * 8;     // halves
    const __half* gA = Ag + (long)(bm * BM) * EE;
    const __half* gB = Wg + (long)(bn * BN) * EE;
    const uint32_t sAb = smem_u32(sA);
    const uint32_t sBb = smem_u32(sB);

    const int NK = EE / BK;             // 32

    auto issue = [&](int kt, int buf) {
        const int kb = kt * BK + lch;
        const uint32_t dA = sAb + buf * STAGE_H * 2 + (lrow * KST + lch) * 2;
        const uint32_t dB = sBb + buf * STAGE_H * 2 + (lrow * KST + lch) * 2;
        cpa16(dA,                gA + (long)lrow * EE + kb);
        cpa16(dA + 64 * KST * 2, gA + (long)(lrow + 64) * EE + kb);
        cpa16(dB,                gB + (long)lrow * EE + kb);
        cpa16(dB + 64 * KST * 2, gB + (long)(lrow + 64) * EE + kb);
    };

    issue(0, 0); cpcommit();
    issue(1, 1); cpcommit();

    float acc[2][8][4];
#pragma unroll
    for (int j = 0; j < 2; j++)
#pragma unroll
        for (int n = 0; n < 8; n++)
#pragma unroll
            for (int v = 0; v < 4; v++) acc[j][n][v] = 0.f;

    for (int kt = 0; kt < NK; kt++) {
        cpwait<1>();
        __syncthreads();
        // prefetch 2 ahead (clamped: keeps every commit group non-empty)
        {
            const int nk = (kt + 2 < NK) ? kt + 2 : NK - 1;
            issue(nk, (kt + 2) % STG);
            cpcommit();
        }
        const __half* cA = sA + (kt % STG) * STAGE_H;
        const __half* cB = sB + (kt % STG) * STAGE_H;
#pragma unroll
        for (int ks = 0; ks < 2; ks++) {
            const int kb = ks * 16;
            uint32_t af[2][4];
#pragma unroll
            for (int j = 0; j < 2; j++) {
                const uint32_t ad = smem_u32(
                    cA + (wm * 32 + j * 16 + (lane & 15)) * KST + kb + (lane >> 4) * 8);
                ldmx4(af[j][0], af[j][1], af[j][2], af[j][3], ad);
            }
            uint32_t bf[8][2];
#pragma unroll
            for (int q = 0; q < 4; q++) {
                const int nrow = wn * 64 + q * 16 + (lane & 7) + ((lane >> 4) << 3);
                const int koff = ((lane >> 3) & 1) * 8;
                const uint32_t ad = smem_u32(cB + nrow * KST + kb + koff);
                ldmx4(bf[2 * q][0], bf[2 * q][1], bf[2 * q + 1][0], bf[2 * q + 1][1], ad);
            }
#pragma unroll
            for (int j = 0; j < 2; j++)
#pragma unroll
                for (int n = 0; n < 8; n++) mma16816(acc[j][n], af[j], bf[n]);
        }
        __syncthreads();
    }

    // Epilogue: + bias, store
#pragma unroll
    for (int j = 0; j < 2; j++) {
#pragma unroll
        for (int n = 0; n < 8; n++) {
            const int row = bm * BM + wm * 32 + j * 16 + (lane >> 2);
            const int col = bn * BN + wn * 64 + n * 8 + (lane & 3) * 2;
            const float b0 = biasg[col], b1 = biasg[col + 1];
            const float c0 = acc[j][n][0] + b0, c1 = acc[j][n][1] + b1;
            const float c2 = acc[j][n][2] + b0, c3 = acc[j][n][3] + b1;
            if (O16) {
                __half* C = (__half*)Cg_;
                *(__half2*)(C + (long)row * EE + col)       = __floats2half2_rn(c0, c1);
                *(__half2*)(C + (long)(row + 8) * EE + col) = __floats2half2_rn(c2, c3);
            } else {
                float* C = (float*)Cg_;
                *(float2*)(C + (long)row * EE + col)       = make_float2(c0, c1);
                *(float2*)(C + (long)(row + 8) * EE + col) = make_float2(c2, c3);
            }
        }
    }
}

__global__ __launch_bounds__(256, 2) void qkv_kernel(const float* bq, const float* bk,
                                                     const float* bv) {
    extern __shared__ __half sm_g[];
    const int z = blockIdx.z;
    const __half* A = g_X[z];
    const __half* W = g_W[z];
    const float* bias = (z == 0) ? bq : (z == 1) ? bk : bv;
    __half* O = (z == 0) ? g_Q : (z == 1) ? g_K : g_V;
    gemm_body<true>(A, W, bias, O, sm_g, sm_g + STG * STAGE_H);
}

__global__ __launch_bounds__(256, 2) void oproj_kernel(const float* bo, float* out) {
    extern __shared__ __half sm_g[];
    gemm_body<false>(g_A, g_W[3], bo, out, sm_g, sm_g + STG * STAGE_H);
}

// ---------------------------------------------------------------------------
// Flash attention: CTA = (b, h, 128 queries), 8 warps x 16 q-rows.
// KV tiles of 64 rows, 3-stage cp.async pipeline, one sync per tile.
// ---------------------------------------------------------------------------
#define QT 128
#define KT 64
#define AST 72                         // padded stride (halves), 144B: 16B-aligned
#define KVSTG_H (KT * AST)             // halves per K (or V) stage

__global__ __launch_bounds__(256, 1) void attn_kernel() {
    extern __shared__ __half sm_a[];
    __half* sQ = sm_a;                         // QT*AST
    __half* sK = sQ + QT * AST;                // 3 stages
    __half* sV = sK + 3 * KVSTG_H;             // 3 stages

    const int tid  = threadIdx.x;
    const int warp = tid >> 5, lane = tid & 31;
    const int qbase = blockIdx.x * QT;
    const int h     = blockIdx.y;
    const int b     = blockIdx.z;
    const long rowbase = (long)b * SS;
    const int colbase  = h * DD;

    const uint32_t sKb = smem_u32(sK);
    const uint32_t sVb = smem_u32(sV);

    // cp.async mapping for KV: 64 rows x 8 chunks(16B); thread -> row=tid/8,
    // chunk=tid&7, rows +0/+32
    const int krow = tid >> 3;
    const int kch  = (tid & 7) * 8;   // halves

    const int NT = SS / KT;           // 32

    auto issueKV = [&](int t, int buf) {
        const long gb = (rowbase + t * KT) * EE + colbase + kch;
        const uint32_t dK = sKb + buf * KVSTG_H * 2 + (krow * AST + kch) * 2;
        const uint32_t dV = sVb + buf * KVSTG_H * 2 + (krow * AST + kch) * 2;
        cpa16(dK,                g_K + gb + (long)krow * EE);
        cpa16(dK + 32 * AST * 2, g_K + gb + (long)(krow + 32) * EE);
        cpa16(dV,                g_V + gb + (long)krow * EE);
        cpa16(dV + 32 * AST * 2, g_V + gb + (long)(krow + 32) * EE);
    };

    issueKV(0, 0); cpcommit();
    issueKV(1, 1); cpcommit();

    // Stage Q tile [128 x 64]
    {
        const int lr = tid >> 3;
        const int lc = (tid & 7) * 8;
#pragma unroll
        for (int i = 0; i < 4; i++) {
            const int row = lr + i * 32;
            const uint4 v = *(const uint4*)(g_Q + (rowbase + qbase + row) * EE + colbase + lc);
            *(uint4*)(sQ + row * AST + lc) = v;
        }
    }
    __syncthreads();

    // Persistent per-warp Q fragments (16 rows x 64 d)
    uint32_t qa[4][4];
    {
        const int wq = warp * 16;
#pragma unroll
        for (int kk = 0; kk < 4; kk++) {
            const uint32_t ad =
                smem_u32(sQ + (wq + (lane & 15)) * AST + kk * 16 + (lane >> 4) * 8);
            ldmx4(qa[kk][0], qa[kk][1], qa[kk][2], qa[kk][3], ad);
        }
    }

    float oacc[8][4];
#pragma unroll
    for (int n = 0; n < 8; n++)
#pragma unroll
        for (int v = 0; v < 4; v++) oacc[n][v] = 0.f;
    float m0 = -1e30f, m1 = -1e30f, l0 = 0.f, l1 = 0.f;

    const float SC = 0.125f * 1.4426950408889634f;  // scale * log2(e)

    for (int t = 0; t < NT; t++) {
        cpwait<1>();
        __syncthreads();
        {
            const int nt = (t + 2 < NT) ? t + 2 : NT - 1;
            issueKV(nt, (t + 2) % 3);
            cpcommit();
        }
        const __half* cK = sK + (t % 3) * KVSTG_H;
        const __half* cV = sV + (t % 3) * KVSTG_H;

        // S = Q K^T : 16 x 64 per warp
        float sacc[8][4];
#pragma unroll
        for (int n = 0; n < 8; n++)
#pragma unroll
            for (int v = 0; v < 4; v++) sacc[n][v] = 0.f;
#pragma unroll
        for (int kk = 0; kk < 4; kk++) {
            uint32_t kb[8][2];
#pragma unroll
            for (int q = 0; q < 4; q++) {
                const int nrow = q * 16 + (lane & 7) + ((lane >> 4) << 3);
                const int koff = ((lane >> 3) & 1) * 8;
                const uint32_t ad = smem_u32(cK + nrow * AST + kk * 16 + koff);
                ldmx4(kb[2 * q][0], kb[2 * q][1], kb[2 * q + 1][0], kb[2 * q + 1][1], ad);
            }
#pragma unroll
            for (int n = 0; n < 8; n++) mma16816(sacc[n], qa[kk], kb[n]);
        }

        // Online softmax
        float mx0 = -1e30f, mx1 = -1e30f;
#pragma unroll
        for (int n = 0; n < 8; n++) {
            mx0 = fmaxf(mx0, fmaxf(sacc[n][0], sacc[n][1]));
            mx1 = fmaxf(mx1, fmaxf(sacc[n][2], sacc[n][3]));
        }
        mx0 = fmaxf(mx0, __shfl_xor_sync(0xffffffffu, mx0, 1));
        mx0 = fmaxf(mx0, __shfl_xor_sync(0xffffffffu, mx0, 2));
        mx1 = fmaxf(mx1, __shfl_xor_sync(0xffffffffu, mx1, 1));
        mx1 = fmaxf(mx1, __shfl_xor_sync(0xffffffffu, mx1, 2));
        const float nm0 = fmaxf(m0, mx0 * SC);
        const float nm1 = fmaxf(m1, mx1 * SC);
        const float cr0 = exp2f(m0 - nm0);
        const float cr1 = exp2f(m1 - nm1);
        m0 = nm0; m1 = nm1;
        l0 *= cr0; l1 *= cr1;
#pragma unroll
        for (int n = 0; n < 8; n++) {
            oacc[n][0] *= cr0; oacc[n][1] *= cr0;
            oacc[n][2] *= cr1; oacc[n][3] *= cr1;
        }
        float rs0 = 0.f, rs1 = 0.f;
        uint32_t pa[8], pb[8];
#pragma unroll
        for (int n = 0; n < 8; n++) {
            const float p0 = exp2f(sacc[n][0] * SC - m0);
            const float p1 = exp2f(sacc[n][1] * SC - m0);
            const float p2 = exp2f(sacc[n][2] * SC - m1);
            const float p3 = exp2f(sacc[n][3] * SC - m1);
            rs0 += p0 + p1; rs1 += p2 + p3;
            const __half2 hp0 = __floats2half2_rn(p0, p1);
            const __half2 hp1 = __floats2half2_rn(p2, p3);
            pa[n] = *(const uint32_t*)&hp0;
            pb[n] = *(const uint32_t*)&hp1;
        }
        rs0 += __shfl_xor_sync(0xffffffffu, rs0, 1);
        rs0 += __shfl_xor_sync(0xffffffffu, rs0, 2);
        rs1 += __shfl_xor_sync(0xffffffffu, rs1, 1);
        rs1 += __shfl_xor_sync(0xffffffffu, rs1, 2);
        l0 += rs0; l1 += rs1;

        // O += P V (P already in A-fragment layout)
#pragma unroll
        for (int kk = 0; kk < 4; kk++) {
            const uint32_t af[4] = {pa[2 * kk], pb[2 * kk], pa[2 * kk + 1], pb[2 * kk + 1]};
            uint32_t vb[8][2];
#pragma unroll
            for (int pr = 0; pr < 4; pr++) {
                const int kvrow = kk * 16 + (((lane >> 3) & 1) << 3) + (lane & 7);
                const int dcol  = pr * 16 + ((lane >> 4) << 3);
                const uint32_t ad = smem_u32(cV + kvrow * AST + dcol);
                ldmx4t(vb[2 * pr][0], vb[2 * pr][1], vb[2 * pr + 1][0], vb[2 * pr + 1][1], ad);
            }
#pragma unroll
            for (int n = 0; n < 8; n++) mma16816(oacc[n], af, vb[n]);
        }
    }

    // Epilogue
    const float il0 = 1.f / l0, il1 = 1.f / l1;
    const int row = qbase + warp * 16 + (lane >> 2);
#pragma unroll
    for (int n = 0; n < 8; n++) {
        const int col = colbase + n * 8 + (lane & 3) * 2;
        *(__half2*)(g_A + (rowbase + row) * EE + col) =
            __floats2half2_rn(oacc[n][0] * il0, oacc[n][1] * il0);
        *(__half2*)(g_A + (rowbase + row + 8) * EE + col) =
            __floats2half2_rn(oacc[n][2] * il1, oacc[n][3] * il1);
    }
}

// ---------------------------------------------------------------------------
// Launch
// ---------------------------------------------------------------------------
extern "C" void kernel_launch(void* const* d_in, const int* in_sizes, int n_in,
                              void* d_out, int out_size) {
    (void)in_sizes; (void)n_in; (void)out_size;
    const float* q  = (const float*)d_in[0];
    const float* k  = (const float*)d_in[1];
    const float* v  = (const float*)d_in[2];
    const float* Wq = (const float*)d_in[3];
    const float* bq = (const float*)d_in[4];
    const float* Wk = (const float*)d_in[5];
    const float* bk = (const float*)d_in[6];
    const float* Wv = (const float*)d_in[7];
    const float* bv = (const float*)d_in[8];
    const float* Wo = (const float*)d_in[9];
    const float* bo = (const float*)d_in[10];

    const int gemm_smem = STG * STAGE_H * 2 * 2;                    // 61440 B
    const int attn_smem = (QT * AST + 6 * KVSTG_H) * 2;             // 73728 B
    cudaFuncSetAttribute(qkv_kernel,  cudaFuncAttributeMaxDynamicSharedMemorySize, gemm_smem);
    cudaFuncSetAttribute(oproj_kernel, cudaFuncAttributeMaxDynamicSharedMemorySize, gemm_smem);
    cudaFuncSetAttribute(attn_kernel, cudaFuncAttributeMaxDynamicSharedMemorySize, attn_smem);

    cvt_kernel<<<4096, 256>>>(q, k, v, Wq, Wk, Wv, Wo);

    dim3 g1(MM / BM, EE / BN, 3);
    qkv_kernel<<<g1, 256, gemm_smem>>>(bq, bk, bv);

    dim3 g2(SS / QT, HH, BB);
    attn_kernel<<<g2, 256, attn_smem>>>();

    dim3 g3(MM / BM, EE / BN, 1);
    oproj_kernel<<<g3, 256, gemm_smem>>>(bo, (float*)d_out);
}